// round 15
// baseline (speedup 1.0000x reference)
#include <cuda_runtime.h>
#include <cuda_bf16.h>
#include <cstdint>
#include <cstddef>
#include <math_constants.h>

#define BB   2
#define SS   2048
#define DD   1024
#define HH   16
#define DH   64
#define BH   (BB*HH)                 // 32
#define ROWS (BB*SS)                 // 4096
#define OUT_ELEMS  ((size_t)BB*SS*DD)        // 4,194,304
#define ATTN_ELEMS ((size_t)BH*SS*SS)        // 134,217,728

// ---------------- scratch ---------------------------------------------------
__device__ float g_ln[3ull * OUT_ELEMS];     // qn,kn,vn (tf32-rounded)
__device__ float g_pr[3ull * OUT_ELEMS];     // qs,ks,vs (tf32-rounded) [BH][S][64]
__device__ float g_ctx[OUT_ELEMS];           // context [B,T,D] (tf32-rounded)
__device__ float g_attn_fb[ATTN_ELEMS];      // fallback attn when not in d_out
__device__ float g_wt[4ull * DD * DD];       // tf32-rounded Wq,Wk,Wv,Wo
__device__ float g_part[(size_t)BH * SS * 16];   // per-block row partial sums
__device__ float g_inv[(size_t)BH * SS];         // 1/rowsum

// ---------------- helpers ---------------------------------------------------
__device__ __forceinline__ uint32_t f2tf32(float x) {
    uint32_t r;
    asm("cvt.rna.tf32.f32 %0, %1;" : "=r"(r) : "f"(x));
    return r;
}
__device__ __forceinline__ float rtf(float x) { return __uint_as_float(f2tf32(x)); }

__device__ __forceinline__ void mma_tf32(float* c, const uint32_t* a, const uint32_t* b) {
    asm volatile(
        "mma.sync.aligned.m16n8k8.row.col.f32.tf32.tf32.f32 "
        "{%0,%1,%2,%3},{%4,%5,%6,%7},{%8,%9},{%0,%1,%2,%3};"
        : "+f"(c[0]), "+f"(c[1]), "+f"(c[2]), "+f"(c[3])
        : "r"(a[0]), "r"(a[1]), "r"(a[2]), "r"(a[3]), "r"(b[0]), "r"(b[1]));
}

#define CP16(dst_u32, src_ptr) \
    asm volatile("cp.async.cg.shared.global [%0], [%1], 16;\n" :: "r"(dst_u32), "l"(src_ptr))
#define CPCOMMIT() asm volatile("cp.async.commit_group;\n" ::)
#define CPWAIT(n)  asm volatile("cp.async.wait_group %0;\n" :: "n"(n))

template <bool ISMAX>
__device__ __forceinline__ float block_reduce(float v) {
    __shared__ float sm[8];
    int tid = threadIdx.x;
#pragma unroll
    for (int o = 16; o; o >>= 1) {
        float other = __shfl_xor_sync(0xffffffffu, v, o);
        v = ISMAX ? fmaxf(v, other) : (v + other);
    }
    if ((tid & 31) == 0) sm[tid >> 5] = v;
    __syncthreads();
    if (tid < 32) {
        float r = (tid < 8) ? sm[tid] : (ISMAX ? -CUDART_INF_F : 0.0f);
#pragma unroll
        for (int o = 4; o; o >>= 1) {
            float other = __shfl_xor_sync(0xffffffffu, r, o);
            r = ISMAX ? fmaxf(r, other) : (r + other);
        }
        if (tid == 0) sm[0] = r;
    }
    __syncthreads();
    float res = sm[0];
    __syncthreads();
    return res;
}

// ---------------- kernel 0: round all 4 weight matrices to tf32 -------------
__global__ __launch_bounds__(256) void roundw4_kernel(
    const float4* __restrict__ s0, const float4* __restrict__ s1,
    const float4* __restrict__ s2, const float4* __restrict__ s3,
    float4* __restrict__ out)
{
    int idx = blockIdx.x * 256 + threadIdx.x;       // 4 * 262144 float4
    int w = idx >> 18;
    const float4* s = (w == 0) ? s0 : (w == 1) ? s1 : (w == 2) ? s2 : s3;
    float4 v = s[idx & 0x3FFFF];
    v.x = rtf(v.x); v.y = rtf(v.y); v.z = rtf(v.z); v.w = rtf(v.w);
    out[idx] = v;
}

// ---------------- kernel 1: LayerNorm (tf32-rounded output) -----------------
__global__ __launch_bounds__(256) void ln_kernel(
    const float* __restrict__ q, const float* __restrict__ k,
    const float* __restrict__ v, const float* __restrict__ gg,
    const float* __restrict__ bb, float* __restrict__ out)
{
    int row = blockIdx.x;
    int which = blockIdx.y;
    const float* x = (which == 0 ? q : (which == 1 ? k : v)) + (size_t)row * DD;
    float* o = out + (size_t)which * OUT_ELEMS + (size_t)row * DD;
    int tid = threadIdx.x;

    float4 xv = reinterpret_cast<const float4*>(x)[tid];
    float s = xv.x + xv.y + xv.z + xv.w;
    float mean = block_reduce<false>(s) * (1.0f / DD);
    float d0 = xv.x - mean, d1 = xv.y - mean, d2 = xv.z - mean, d3 = xv.w - mean;
    float ss = d0 * d0 + d1 * d1 + d2 * d2 + d3 * d3;
    float var = block_reduce<false>(ss) * (1.0f / DD);
    float rstd = rsqrtf(var + 1e-5f);

    float4 gv = reinterpret_cast<const float4*>(gg)[tid];
    float4 bv = reinterpret_cast<const float4*>(bb)[tid];
    float4 ov;
    ov.x = rtf(d0 * rstd * gv.x + bv.x);
    ov.y = rtf(d1 * rstd * gv.y + bv.y);
    ov.z = rtf(d2 * rstd * gv.z + bv.z);
    ov.w = rtf(d3 * rstd * gv.w + bv.w);
    reinterpret_cast<float4*>(o)[tid] = ov;
}

// ---------------- kernel 2: 128x128x32 tf32 GEMM, cp.async, 1 sync/chunk ----
#define SA 40
template <int EPI>
__global__ __launch_bounds__(256, 2) void gemm2(
    const float* __restrict__ A0, const float* __restrict__ B0,
    const float* __restrict__ b0, const float* __restrict__ b1,
    const float* __restrict__ b2, float* __restrict__ C0, float scale0)
{
    extern __shared__ float smd[];
    float* As = smd;              // 2 x 128*40
    float* Bs = smd + 2 * 128 * SA;

    const int z = blockIdx.z;
    const float* A    = A0 + (size_t)z * OUT_ELEMS;
    const float* Bm   = B0 + (size_t)z * DD * DD;
    const float* bias = (z == 0) ? b0 : (z == 1) ? b1 : b2;
    float* C          = C0 + (size_t)z * OUT_ELEMS;
    const float scale = (EPI == 0 && z == 0) ? scale0 : 1.0f;

    const int m0 = blockIdx.y * 128, n0 = blockIdx.x * 128;
    const int tid = threadIdx.x, lane = tid & 31, warp = tid >> 5;
    const int g = lane >> 2, l4 = lane & 3;
    const int wtm = (warp & 1) * 64, wtn = (warp >> 1) * 32;

    float acc[4][4][4];
#pragma unroll
    for (int i = 0; i < 4; i++)
#pragma unroll
        for (int j = 0; j < 4; j++)
#pragma unroll
            for (int e = 0; e < 4; e++) acc[i][j][e] = 0.0f;

    const int ar = tid >> 3;
    const int ac = (tid & 7) * 4;
    uint32_t sAu = (uint32_t)__cvta_generic_to_shared(As);
    uint32_t sBu = (uint32_t)__cvta_generic_to_shared(Bs);

    auto stage = [&](int chunk, int buf) {
        const float* Ap = A + (size_t)m0 * 1024 + chunk * 32;
        const float* Bp = Bm + (size_t)n0 * 1024 + chunk * 32;
        uint32_t da = sAu + (uint32_t)(buf * 128 * SA) * 4;
        uint32_t db = sBu + (uint32_t)(buf * 128 * SA) * 4;
#pragma unroll
        for (int i = 0; i < 4; i++) {
            int r = ar + i * 32;
            CP16(da + (uint32_t)(r * SA + ac) * 4, Ap + (size_t)r * 1024 + ac);
            CP16(db + (uint32_t)(r * SA + ac) * 4, Bp + (size_t)r * 1024 + ac);
        }
    };

    auto domma = [&](int buf) {
        const float* Ab = As + buf * 128 * SA;
        const float* Bb = Bs + buf * 128 * SA;
#pragma unroll
        for (int kk = 0; kk < 32; kk += 8) {
            int kc = kk + 2 * l4;
            uint32_t af[4][4], bf[4][2];
#pragma unroll
            for (int i = 0; i < 4; i++) {
                int r = wtm + i * 16 + g;
                uint2 p0 = *(const uint2*)&Ab[r * SA + kc];
                uint2 p1 = *(const uint2*)&Ab[(r + 8) * SA + kc];
                af[i][0] = p0.x; af[i][2] = p0.y;
                af[i][1] = p1.x; af[i][3] = p1.y;
            }
#pragma unroll
            for (int j = 0; j < 4; j++) {
                int cN = wtn + j * 8 + g;
                uint2 p = *(const uint2*)&Bb[cN * SA + kc];
                bf[j][0] = p.x; bf[j][1] = p.y;
            }
#pragma unroll
            for (int i = 0; i < 4; i++)
#pragma unroll
                for (int j = 0; j < 4; j++)
                    mma_tf32(acc[i][j], af[i], bf[j]);
        }
    };

    stage(0, 0); CPCOMMIT();
    int buf = 0;
    for (int c = 0; c < 32; c++) {
        CPWAIT(0);
        __syncthreads();
        if (c + 1 < 32) { stage(c + 1, buf ^ 1); CPCOMMIT(); }
        domma(buf);
        buf ^= 1;
    }

#pragma unroll
    for (int i = 0; i < 4; i++) {
        int m = m0 + wtm + i * 16 + g;
#pragma unroll
        for (int j = 0; j < 4; j++) {
            int n = n0 + wtn + j * 8 + 2 * l4;
            float2 bv = *(const float2*)&bias[n];
            float v0 = (acc[i][j][0] + bv.x) * scale;
            float v1 = (acc[i][j][1] + bv.y) * scale;
            float v2 = (acc[i][j][2] + bv.x) * scale;
            float v3 = (acc[i][j][3] + bv.y) * scale;
            if (EPI == 0) {
                v0 = rtf(v0); v1 = rtf(v1); v2 = rtf(v2); v3 = rtf(v3);
                int h = n >> 6, d = n & 63;
                size_t base0 = (((size_t)(m >> 11) * HH + h) * SS + (m & 2047)) * DH + d;
                size_t base1 = (((size_t)((m + 8) >> 11) * HH + h) * SS + ((m + 8) & 2047)) * DH + d;
                *(float2*)&C[base0] = make_float2(v0, v1);
                *(float2*)&C[base1] = make_float2(v2, v3);
            } else {
                *(float2*)&C[(size_t)m * DD + n] = make_float2(v0, v1);
                *(float2*)&C[(size_t)(m + 8) * DD + n] = make_float2(v2, v3);
            }
        }
    }
}

// ---------------- kernel 3: QK^T + exp -> row-sum partials ONLY --------------
// No score materialization. Upper blocks zero-fill attn output.
#define SQ 72
__global__ __launch_bounds__(256, 2) void qk_kernel(
    const float* __restrict__ Q, const float* __restrict__ Kt,
    float* __restrict__ attnOut, float* __restrict__ part)
{
    const int n0 = blockIdx.x * 128, m0 = blockIdx.y * 128, z = blockIdx.z;
    const long zo = (long)z * SS;
    const int tid = threadIdx.x;

    if (n0 > m0) {                       // strictly above diagonal: zeros
        float4 zz = make_float4(0.f, 0.f, 0.f, 0.f);
#pragma unroll
        for (int t = 0; t < 16; t++) {
            int idx = tid + t * 256;
            int r = idx >> 5, c = (idx & 31) * 4;
            *(float4*)&attnOut[(zo + m0 + r) * SS + n0 + c] = zz;
        }
        return;
    }

    extern __shared__ float smd[];
    float* As = smd;                 // 128*72
    float* Bs = smd + 128 * SQ;

    const int lane = tid & 31, warp = tid >> 5;
    const int g = lane >> 2, l4 = lane & 3;
    const int wtm = (warp & 1) * 64, wtn = (warp >> 1) * 32, wn = warp >> 1;

#pragma unroll
    for (int t = 0; t < 8; t++) {
        int idx = tid + t * 256;
        int r = idx >> 4, c = (idx & 15) * 4;
        *(float4*)&As[r * SQ + c] = *(const float4*)&Q[(zo + m0 + r) * DH + c];
        *(float4*)&Bs[r * SQ + c] = *(const float4*)&Kt[(zo + n0 + r) * DH + c];
    }
    __syncthreads();

    float acc[4][4][4];
#pragma unroll
    for (int i = 0; i < 4; i++)
#pragma unroll
        for (int j = 0; j < 4; j++)
#pragma unroll
            for (int e = 0; e < 4; e++) acc[i][j][e] = 0.0f;

#pragma unroll
    for (int kk = 0; kk < 64; kk += 8) {
        int kc = kk + 2 * l4;
        uint32_t af[4][4], bf[4][2];
#pragma unroll
        for (int i = 0; i < 4; i++) {
            int r = wtm + i * 16 + g;
            uint2 p0 = *(const uint2*)&As[r * SQ + kc];
            uint2 p1 = *(const uint2*)&As[(r + 8) * SQ + kc];
            af[i][0] = p0.x; af[i][2] = p0.y;
            af[i][1] = p1.x; af[i][3] = p1.y;
        }
#pragma unroll
        for (int j = 0; j < 4; j++) {
            int cN = wtn + j * 8 + g;
            uint2 p = *(const uint2*)&Bs[cN * SQ + kc];
            bf[j][0] = p.x; bf[j][1] = p.y;
        }
#pragma unroll
        for (int i = 0; i < 4; i++)
#pragma unroll
            for (int j = 0; j < 4; j++)
                mma_tf32(acc[i][j], af[i], bf[j]);
    }

    // epilogue: exp + mask -> row sums (no stores of scores)
    float rs[4][2];
#pragma unroll
    for (int i = 0; i < 4; i++) { rs[i][0] = 0.f; rs[i][1] = 0.f; }

#pragma unroll
    for (int i = 0; i < 4; i++) {
        int r0 = m0 + wtm + i * 16 + g;
#pragma unroll
        for (int j = 0; j < 4; j++) {
            int c0 = n0 + wtn + j * 8 + 2 * l4;
            float e0 = (c0     <= r0    ) ? __expf(acc[i][j][0]) : 0.f;
            float e1 = (c0 + 1 <= r0    ) ? __expf(acc[i][j][1]) : 0.f;
            float e2 = (c0     <= r0 + 8) ? __expf(acc[i][j][2]) : 0.f;
            float e3 = (c0 + 1 <= r0 + 8) ? __expf(acc[i][j][3]) : 0.f;
            rs[i][0] += e0 + e1;
            rs[i][1] += e2 + e3;
        }
    }
#pragma unroll
    for (int i = 0; i < 4; i++)
#pragma unroll
        for (int h = 0; h < 2; h++) {
            float v = rs[i][h];
            v += __shfl_xor_sync(0xffffffffu, v, 1);
            v += __shfl_xor_sync(0xffffffffu, v, 2);
            rs[i][h] = v;
        }
    __syncthreads();
    float* red = smd;                // [128][4]
    if (l4 == 0) {
#pragma unroll
        for (int i = 0; i < 4; i++) {
            red[(wtm + i * 16 + g) * 4 + wn]     = rs[i][0];
            red[(wtm + i * 16 + g + 8) * 4 + wn] = rs[i][1];
        }
    }
    __syncthreads();
    if (tid < 128) {
        float s = red[tid * 4] + red[tid * 4 + 1] + red[tid * 4 + 2] + red[tid * 4 + 3];
        part[(zo + m0 + tid) * 16 + (n0 >> 7)] = s;
    }
}

// ---------------- kernel 4: row-sum reduce -> reciprocal --------------------
__global__ __launch_bounds__(256) void rowsum_kernel(
    const float* __restrict__ part, float* __restrict__ inv)
{
    int idx = blockIdx.x * 256 + threadIdx.x;    // < 65536
    int t = idx & (SS - 1);
    int nb = (t >> 7) + 1;
    float s = 0.f;
    for (int b = 0; b < nb; b++) s += part[(size_t)idx * 16 + b];
    inv[idx] = 1.0f / s;
}

// ---------------- kernel 5: fused recompute-QK + exp + attn write + PV ------
// Per CTA: (m-block reverse order, z). Q frags in regs; K,V chunks in smem.
// Score accumulator fragments are reused DIRECTLY as PV A-operand fragments
// (identical thread->element mapping under the adjacent-k remap).
#define PKS 72
#define KCH (32 * PKS)     // K chunk floats (padded)
#define VCH (32 * 64)      // V chunk floats
__global__ __launch_bounds__(256, 2) void pv2_kernel(
    const float* __restrict__ Q, const float* __restrict__ Kt,
    const float* __restrict__ V, const float* __restrict__ inv,
    float* __restrict__ attnOut, float* __restrict__ ctx)
{
    const int m0 = (15 - blockIdx.x) * 128, z = blockIdx.y;
    const long zo = (long)z * SS;
    const int tid = threadIdx.x, lane = tid & 31, warp = tid >> 5;
    const int g = lane >> 2, l4 = lane & 3;
    const int r0 = m0 + warp * 16 + g;           // this thread's base row

    extern __shared__ float smd[];
    float* Ks = smd;                  // 2 x 32*PKS
    float* Vs = smd + 2 * KCH;        // 2 x 32*64
    uint32_t Ku = (uint32_t)__cvta_generic_to_shared(Ks);
    uint32_t Vu = (uint32_t)__cvta_generic_to_shared(Vs);

    // Q fragments (K=64 -> 8 k-steps), held in registers for all chunks
    uint32_t qf[8][4];
#pragma unroll
    for (int s = 0; s < 8; s++) {
        int kc = 8 * s + 2 * l4;
        uint2 a = *(const uint2*)&Q[(size_t)(zo + r0) * DH + kc];
        uint2 b = *(const uint2*)&Q[(size_t)(zo + r0 + 8) * DH + kc];
        qf[s][0] = a.x; qf[s][2] = a.y;
        qf[s][1] = b.x; qf[s][3] = b.y;
    }
    const float iv0 = inv[zo + r0];
    const float iv1 = inv[zo + r0 + 8];

    float oacc[8][4];
#pragma unroll
    for (int j = 0; j < 8; j++)
#pragma unroll
        for (int e = 0; e < 4; e++) oacc[j][e] = 0.0f;

    const int NC = (m0 >> 5) + 4;

    // staging: K chunk 32x64 (pad 72), V chunk 32x64 rotate-4 swizzled
    auto stage = [&](int c, int buf) {
        int k0 = c * 32;
#pragma unroll
        for (int t = 0; t < 2; t++) {
            int idx = tid + t * 256;              // 0..511
            int kr = idx >> 4, kcol = (idx & 15) * 4;
            CP16(Ku + (uint32_t)(buf * KCH + kr * PKS + kcol) * 4,
                 &Kt[(size_t)(zo + k0 + kr) * DH + kcol]);
            int cpv = (kcol + 4 * kr) & 63;
            CP16(Vu + (uint32_t)(buf * VCH + kr * 64 + cpv) * 4,
                 &V[(size_t)(zo + k0 + kr) * DH + kcol]);
        }
    };

    stage(0, 0); CPCOMMIT();
    for (int c = 0; c < NC; c++) {
        int buf = c & 1;
        CPWAIT(0);
        __syncthreads();
        if (c + 1 < NC) { stage(c + 1, buf ^ 1); CPCOMMIT(); }
        const float* Kb = Ks + buf * KCH;
        const float* Vb = Vs + buf * VCH;
        const int k0 = c * 32;

        // ---- QK scores for 16 rows x 32 cols (this warp) ----
        float sacc[4][4];
#pragma unroll
        for (int j = 0; j < 4; j++)
#pragma unroll
            for (int e = 0; e < 4; e++) sacc[j][e] = 0.0f;
#pragma unroll
        for (int s = 0; s < 8; s++) {
            int kc = 8 * s + 2 * l4;
            uint32_t bf[4][2];
#pragma unroll
            for (int j = 0; j < 4; j++) {
                int cN = 8 * j + g;
                uint2 p = *(const uint2*)&Kb[cN * PKS + kc];
                bf[j][0] = p.x; bf[j][1] = p.y;
            }
#pragma unroll
            for (int j = 0; j < 4; j++)
                mma_tf32(sacc[j], qf[s], bf[j]);
        }

        // ---- exp + mask + normalize, write attn, build PV A-frags ----
        uint32_t afp[4][4];
#pragma unroll
        for (int j = 0; j < 4; j++) {
            int ncol = k0 + 8 * j + 2 * l4;
            float e0 = (ncol     <= r0    ) ? __expf(sacc[j][0]) : 0.f;
            float e1 = (ncol + 1 <= r0    ) ? __expf(sacc[j][1]) : 0.f;
            float e2 = (ncol     <= r0 + 8) ? __expf(sacc[j][2]) : 0.f;
            float e3 = (ncol + 1 <= r0 + 8) ? __expf(sacc[j][3]) : 0.f;
            float f0 = e0 * iv0, f1 = e1 * iv0;
            float f2 = e2 * iv1, f3 = e3 * iv1;
            *(float2*)&attnOut[(size_t)(zo + r0) * SS + ncol]     = make_float2(f0, f1);
            *(float2*)&attnOut[(size_t)(zo + r0 + 8) * SS + ncol] = make_float2(f2, f3);
            afp[j][0] = f2tf32(f0); afp[j][2] = f2tf32(f1);
            afp[j][1] = f2tf32(f2); afp[j][3] = f2tf32(f3);
        }

        // ---- PV: out(16x64) += attn(16x32) x V(32x64) ----
#pragma unroll
        for (int t = 0; t < 4; t++) {
            int kc = 8 * t + 2 * l4;
            int rot0 = 4 * kc, rot1 = 4 * (kc + 1);
#pragma unroll
            for (int j2 = 0; j2 < 8; j2++) {
                int cN2 = 8 * j2 + g;
                uint32_t bf[2];
                bf[0] = __float_as_uint(Vb[kc * 64 + ((cN2 + rot0) & 63)]);
                bf[1] = __float_as_uint(Vb[(kc + 1) * 64 + ((cN2 + rot1) & 63)]);
                mma_tf32(oacc[j2], afp[t], bf);
            }
        }
    }

    // ---- epilogue -> ctx [B,T,D], tf32-rounded ----
    const int b = z >> 4, h = z & 15;
#pragma unroll
    for (int j2 = 0; j2 < 8; j2++) {
        int col = 8 * j2 + 2 * l4;
        size_t ob = ((size_t)b * SS + r0) * DD + h * DH + col;
        *(float2*)&ctx[ob]          = make_float2(rtf(oacc[j2][0]), rtf(oacc[j2][1]));
        *(float2*)&ctx[ob + 8 * DD] = make_float2(rtf(oacc[j2][2]), rtf(oacc[j2][3]));
    }
}

// ---------------- launch -----------------------------------------------------
extern "C" void kernel_launch(void* const* d_in, const int* in_sizes, int n_in,
                              void* d_out, int out_size)
{
    (void)in_sizes; (void)n_in;
    const float* q    = (const float*)d_in[0];
    const float* k    = (const float*)d_in[1];
    const float* v    = (const float*)d_in[2];
    const float* Wq   = (const float*)d_in[3];
    const float* bq   = (const float*)d_in[4];
    const float* Wk   = (const float*)d_in[5];
    const float* bk   = (const float*)d_in[6];
    const float* Wv   = (const float*)d_in[7];
    const float* bv   = (const float*)d_in[8];
    const float* Wo   = (const float*)d_in[9];
    const float* bo   = (const float*)d_in[10];
    const float* ln_g = (const float*)d_in[11];
    const float* ln_b = (const float*)d_in[12];

    float *ln_buf, *pr_buf, *ctx_buf, *fb_buf, *wt_buf, *part_buf, *inv_buf;
    cudaGetSymbolAddress((void**)&ln_buf,   g_ln);
    cudaGetSymbolAddress((void**)&pr_buf,   g_pr);
    cudaGetSymbolAddress((void**)&ctx_buf,  g_ctx);
    cudaGetSymbolAddress((void**)&fb_buf,   g_attn_fb);
    cudaGetSymbolAddress((void**)&wt_buf,   g_wt);
    cudaGetSymbolAddress((void**)&part_buf, g_part);
    cudaGetSymbolAddress((void**)&inv_buf,  g_inv);

    float* out = (float*)d_out;
    float* attnOut = ((size_t)out_size >= OUT_ELEMS + ATTN_ELEMS)
                        ? out + OUT_ELEMS
                        : fb_buf;

    float* wo = wt_buf + 3ull * DD * DD;

    cudaFuncSetAttribute(gemm2<0>, cudaFuncAttributeMaxDynamicSharedMemorySize, 4 * 128 * SA * 4);
    cudaFuncSetAttribute(gemm2<1>, cudaFuncAttributeMaxDynamicSharedMemorySize, 4 * 128 * SA * 4);
    cudaFuncSetAttribute(qk_kernel, cudaFuncAttributeMaxDynamicSharedMemorySize, 2 * 128 * SQ * 4);
    cudaFuncSetAttribute(pv2_kernel, cudaFuncAttributeMaxDynamicSharedMemorySize,
                         (2 * KCH + 2 * VCH) * 4);

    // 0. Pre-round all 4 weight matrices to tf32
    roundw4_kernel<<<4096, 256>>>((const float4*)Wq, (const float4*)Wk,
                                  (const float4*)Wv, (const float4*)Wo,
                                  (float4*)wt_buf);

    // 1. LayerNorm (tf32-rounded output)
    ln_kernel<<<dim3(ROWS, 3), 256>>>(q, k, v, ln_g, ln_b, ln_buf);

    // 2. All 3 projections in ONE launch
    size_t gsm = 4 * 128 * SA * 4;
    gemm2<0><<<dim3(8, 32, 3), 256, gsm>>>(ln_buf, wt_buf, bq, bk, bv, pr_buf, 0.125f);

    float* qs = pr_buf;
    float* ks = pr_buf + OUT_ELEMS;
    float* vs = pr_buf + 2 * OUT_ELEMS;

    // 3. QK^T + exp -> row-sum partials only (+ zero-fill upper attn)
    qk_kernel<<<dim3(16, 16, 32), 256, 2 * 128 * SQ * 4>>>(qs, ks, attnOut, part_buf);

    // 4. Row sums -> reciprocals
    rowsum_kernel<<<256, 256>>>(part_buf, inv_buf);

    // 5. Fused recompute-QK + normalize + attn write + PV
    pv2_kernel<<<dim3(16, 32), 256, (2 * KCH + 2 * VCH) * 4>>>(
        qs, ks, vs, inv_buf, attnOut, ctx_buf);

    // 6. Output projection (exact output)
    gemm2<1><<<dim3(8, 32, 1), 256, gsm>>>(ctx_buf, wo, bo, bo, bo, out, 1.0f);
}